// round 3
// baseline (speedup 1.0000x reference)
#include <cuda_runtime.h>
#include <cstdint>

// Problem constants
#define BB   16
#define CC   128
#define NN   4096
#define TT   12
#define FF   32
#define JJ   6144      // B*F*T columns
#define KT   16384     // 4*N contraction length

// GEMM tiling
#define BM   128
#define BN   128
#define BK   16
#define BKP  20        // BK + 4 pad  (conflict-free A frag loads)
#define BNP  136       // BN + 8 pad  (conflict-free B frag loads)
#define NIT  (KT / BK) // 1024 k-iterations

// Packed/transposed X scratch: [q*4096+m][j], tf32-rounded, j contiguous.
__device__ float g_Xt[(size_t)KT * JJ];

__device__ __forceinline__ float to_tf32(float x) {
    float r;
    asm("cvt.rna.tf32.f32 %0, %1;" : "=f"(r) : "f"(x));
    return r;
}

__device__ __forceinline__ void mma_tf32(float* d, const uint32_t* a, const uint32_t* b) {
    asm volatile(
        "mma.sync.aligned.m16n8k8.row.col.f32.tf32.tf32.f32 "
        "{%0,%1,%2,%3}, {%4,%5,%6,%7}, {%8,%9}, {%0,%1,%2,%3};\n"
        : "+f"(d[0]), "+f"(d[1]), "+f"(d[2]), "+f"(d[3])
        : "r"(a[0]), "r"(a[1]), "r"(a[2]), "r"(a[3]),
          "r"(b[0]), "r"(b[1]));
}

// ---------------------------------------------------------------------------
// Pre-pass: pack x[b, q*32+f, m, t] -> Xt[q*4096+m][ (b*32+f)*12+t ], tf32.
// ---------------------------------------------------------------------------
__global__ void pack_x_kernel(const float* __restrict__ x) {
    int j   = blockIdx.x * blockDim.x + threadIdx.x; // 0..6143
    int row = blockIdx.y;                            // 0..16383
    int q = row >> 12;
    int m = row & 4095;
    int b   = j / 384;
    int rem = j - b * 384;
    int f   = rem / 12;
    int t   = rem - f * 12;
    float v = x[(((size_t)(b * CC + q * FF + f)) * NN + m) * TT + t];
    g_Xt[(size_t)row * JJ + j] = to_tf32(v);
}

// ---------------------------------------------------------------------------
// Main GEMM: Out_p[n, j] = sum_q s[p][q] * A_{m(p,q)}[n, :] @ Xq[:, j]
// CTA: 128x128 output tile, 256 threads (8 warps, 2x4 of 64x32 warp tiles).
// ---------------------------------------------------------------------------
__global__ void __launch_bounds__(256, 1)
quat_gemm_kernel(const float* __restrict__ Ar, const float* __restrict__ Ai,
                 const float* __restrict__ Aj, const float* __restrict__ Ak,
                 float* __restrict__ out) {
    // L2-friendly block swizzle: within a wave, 8 n-tiles x 4 p share A rows
    // and a handful of j-tiles share X columns (~106 MB working set < L2).
    const int per_group = 8 * 4 * 48;             // 1536
    int bid  = blockIdx.x;
    int g    = bid / per_group;
    int r    = bid - g * per_group;
    int n_in = r & 7;
    int p    = (r >> 3) & 3;
    int jt   = r >> 5;                            // 0..47
    int nt   = g * 8 + n_in;                      // 0..31
    const int n0 = nt * BM;
    const int j0 = jt * BN;

    // Per-q matrix pointer + sign for this output quarter p.
    const float *P0, *P1, *P2, *P3;
    float S0, S1, S2, S3;
    switch (p) {
        case 0:  P0 = Ar; S0 =  1.f; P1 = Ai; S1 = -1.f; P2 = Aj; S2 = -1.f; P3 = Ak; S3 = -1.f; break;
        case 1:  P0 = Ai; S0 =  1.f; P1 = Ar; S1 =  1.f; P2 = Ak; S2 = -1.f; P3 = Aj; S3 =  1.f; break;
        case 2:  P0 = Aj; S0 =  1.f; P1 = Ak; S1 =  1.f; P2 = Ar; S2 =  1.f; P3 = Ai; S3 = -1.f; break;
        default: P0 = Ak; S0 =  1.f; P1 = Aj; S1 = -1.f; P2 = Ai; S2 =  1.f; P3 = Ar; S3 =  1.f; break;
    }

    __shared__ __align__(16) float sA[2][BM * BKP]; // [m][k] , k contiguous
    __shared__ __align__(16) float sX[2][BK * BNP]; // [k][j] , j contiguous

    const int tid  = threadIdx.x;
    const int lane = tid & 31;
    const int wid  = tid >> 5;
    const int wm   = wid >> 2;  // 0..1
    const int wn   = wid & 3;   // 0..3

    // g2s copy assignments
    const int rA0 = tid >> 2;          // A rows 0..63 (+64 for second)
    const int cA4 = (tid & 3) << 2;    // A k-col (x4)
    const int rX0 = tid >> 5;          // X rows 0..7 (+8 for second)
    const int cX4 = (tid & 31) << 2;   // X j-col (x4)

    float acc[4][4][4];
    #pragma unroll
    for (int mi = 0; mi < 4; ++mi)
        #pragma unroll
        for (int ni = 0; ni < 4; ++ni)
            #pragma unroll
            for (int e = 0; e < 4; ++e) acc[mi][ni][e] = 0.f;

    float4 aA0, aA1, aX0, aX1;
    float sg = S0;

    // fetch tile `it` into staging registers
    auto fetch = [&](int it) {
        int k0 = it * BK;
        int q  = k0 >> 12;
        const float* Ag = (q == 0) ? P0 : (q == 1) ? P1 : (q == 2) ? P2 : P3;
        sg              = (q == 0) ? S0 : (q == 1) ? S1 : (q == 2) ? S2 : S3;
        int m0 = k0 & 4095;
        aA0 = *(const float4*)(Ag + (size_t)(n0 + rA0)      * NN + m0 + cA4);
        aA1 = *(const float4*)(Ag + (size_t)(n0 + rA0 + 64) * NN + m0 + cA4);
        aX0 = *(const float4*)(g_Xt + (size_t)(k0 + rX0)     * JJ + j0 + cX4);
        aX1 = *(const float4*)(g_Xt + (size_t)(k0 + rX0 + 8) * JJ + j0 + cX4);
    };

    auto store = [&](int buf) {
        float4 v;
        v.x = to_tf32(aA0.x); v.y = to_tf32(aA0.y); v.z = to_tf32(aA0.z); v.w = to_tf32(aA0.w);
        *(float4*)&sA[buf][rA0 * BKP + cA4] = v;
        v.x = to_tf32(aA1.x); v.y = to_tf32(aA1.y); v.z = to_tf32(aA1.z); v.w = to_tf32(aA1.w);
        *(float4*)&sA[buf][(rA0 + 64) * BKP + cA4] = v;
        v.x = aX0.x * sg; v.y = aX0.y * sg; v.z = aX0.z * sg; v.w = aX0.w * sg;
        *(float4*)&sX[buf][rX0 * BNP + cX4] = v;
        v.x = aX1.x * sg; v.y = aX1.y * sg; v.z = aX1.z * sg; v.w = aX1.w * sg;
        *(float4*)&sX[buf][(rX0 + 8) * BNP + cX4] = v;
    };

    // Prologue
    fetch(0);
    store(0);
    __syncthreads();

    int buf = 0;
    for (int it = 0; it < NIT; ++it) {
        const bool more = (it + 1 < NIT);
        if (more) fetch(it + 1);

        // compute on smem[buf]
        #pragma unroll
        for (int kk = 0; kk < BK; kk += 8) {
            uint32_t afr[4][4];
            uint32_t bfr[4][2];
            #pragma unroll
            for (int mi = 0; mi < 4; ++mi) {
                int rr = wm * 64 + mi * 16 + (lane >> 2);
                const float* base = &sA[buf][rr * BKP + kk + (lane & 3)];
                afr[mi][0] = __float_as_uint(base[0]);
                afr[mi][1] = __float_as_uint(base[8 * BKP]);
                afr[mi][2] = __float_as_uint(base[4]);
                afr[mi][3] = __float_as_uint(base[8 * BKP + 4]);
            }
            #pragma unroll
            for (int ni = 0; ni < 4; ++ni) {
                int cc = wn * 32 + ni * 8 + (lane >> 2);
                const float* base = &sX[buf][(kk + (lane & 3)) * BNP + cc];
                bfr[ni][0] = __float_as_uint(base[0]);
                bfr[ni][1] = __float_as_uint(base[4 * BNP]);
            }
            #pragma unroll
            for (int mi = 0; mi < 4; ++mi)
                #pragma unroll
                for (int ni = 0; ni < 4; ++ni)
                    mma_tf32(acc[mi][ni], afr[mi], bfr[ni]);
        }

        if (more) store(buf ^ 1);
        __syncthreads();
        buf ^= 1;
    }

    // Epilogue: scatter to out[b, p*32+f, n, t] with j = (b*32+f)*12 + t
    #pragma unroll
    for (int mi = 0; mi < 4; ++mi) {
        int rbase = n0 + wm * 64 + mi * 16 + (lane >> 2);
        #pragma unroll
        for (int ni = 0; ni < 4; ++ni) {
            int jb = j0 + wn * 32 + ni * 8 + ((lane & 3) << 1);
            #pragma unroll
            for (int e = 0; e < 4; ++e) {
                int n = rbase + ((e >= 2) ? 8 : 0);
                int j = jb + (e & 1);
                int b   = j / 384;
                int rem = j - b * 384;
                int f   = rem / 12;
                int t   = rem - f * 12;
                out[(((size_t)(b * CC + p * FF + f)) * NN + n) * TT + t] = acc[mi][ni][e];
            }
        }
    }
}

// ---------------------------------------------------------------------------
// Launch
// ---------------------------------------------------------------------------
extern "C" void kernel_launch(void* const* d_in, const int* in_sizes, int n_in,
                              void* d_out, int out_size) {
    const float* x  = (const float*)d_in[0];
    const float* Ar = (const float*)d_in[1];
    const float* Ai = (const float*)d_in[2];
    const float* Aj = (const float*)d_in[3];
    const float* Ak = (const float*)d_in[4];
    float* out = (float*)d_out;

    // 1) pack/transpose x into tf32 scratch [16384][6144]
    dim3 pgrid(JJ / 256, KT);
    pack_x_kernel<<<pgrid, 256>>>(x);

    // 2) quaternion block GEMM: 32 n-tiles * 48 j-tiles * 4 quarters
    quat_gemm_kernel<<<32 * 48 * 4, 256>>>(Ar, Ai, Aj, Ak, out);
}

// round 8
// speedup vs baseline: 1.4973x; 1.4973x over previous
#include <cuda_runtime.h>
#include <cstdint>

// ---------------------------------------------------------------------------
// Problem sizes
// ---------------------------------------------------------------------------
#define NNODE 4096
#define TT    12
#define JJ    6144           // B*F*T columns
#define KT    16384          // 4*N contraction
// GEMM tiling
#define BM    128
#define BN    256
#define BK    16
#define NIT   (KT / BK)      // 1024
#define STAGES 4
#define A_ROW 20             // floats per A smem row (pad: conflict-free frags, 16B-aligned rows)
#define B_ROW 264            // floats per B smem row (pad: conflict-free frags, 16B-aligned rows)
#define A_STAGE_B (BM * A_ROW * 4)     // 10240
#define B_STAGE_B (BK * B_ROW * 4)     // 16896
#define STAGE_B   (A_STAGE_B + B_STAGE_B)
#define SMEM_DYN  (STAGES * STAGE_B)   // 108544

// Scratch: signed tf32 A-tilde per output quarter [p][n][k]; X [k][j] tf32.
__device__ float g_At[(size_t)4 * NNODE * KT];
__device__ float g_Xt[(size_t)KT * JJ];

__device__ __forceinline__ float to_tf32(float x) {
    float r; asm("cvt.rna.tf32.f32 %0, %1;" : "=f"(r) : "f"(x)); return r;
}
__device__ __forceinline__ uint32_t smem_u32(const void* p) {
    uint32_t a;
    asm("{ .reg .u64 t; cvta.to.shared.u64 t, %1; cvt.u32.u64 %0, t; }" : "=r"(a) : "l"(p));
    return a;
}
__device__ __forceinline__ void cp_async16(uint32_t dst, const void* src) {
    asm volatile("cp.async.cg.shared.global [%0], [%1], 16;" :: "r"(dst), "l"(src));
}
__device__ __forceinline__ void mma_tf32(float* d, const uint32_t* a, const uint32_t* b) {
    asm volatile(
        "mma.sync.aligned.m16n8k8.row.col.f32.tf32.tf32.f32 "
        "{%0,%1,%2,%3}, {%4,%5,%6,%7}, {%8,%9}, {%0,%1,%2,%3};\n"
        : "+f"(d[0]), "+f"(d[1]), "+f"(d[2]), "+f"(d[3])
        : "r"(a[0]), "r"(a[1]), "r"(a[2]), "r"(a[3]), "r"(b[0]), "r"(b[1]));
}

// ---------------------------------------------------------------------------
// Prepass 1: g_At[p][n][qv*4096+m] = sign * round_tf32(A_g[n][m])
// (Hamilton table verified against reference: for source g, output quarter p,
//  it lands at k-segment qv[g][p] with sign sv[g][p].)
// ---------------------------------------------------------------------------
__global__ void __launch_bounds__(256, 4) pack_A_kernel(
    const float* __restrict__ Ar, const float* __restrict__ Ai,
    const float* __restrict__ Aj, const float* __restrict__ Ak)
{
    const int n = blockIdx.x;
    const int g = blockIdx.y;
    const float* Ag = (g == 0) ? Ar : (g == 1) ? Ai : (g == 2) ? Aj : Ak;

    int qv[4]; float sv[4];
    switch (g) {
        case 0:  qv[0]=0; qv[1]=1; qv[2]=2; qv[3]=3; sv[0]= 1; sv[1]= 1; sv[2]= 1; sv[3]= 1; break;
        case 1:  qv[0]=1; qv[1]=0; qv[2]=3; qv[3]=2; sv[0]=-1; sv[1]= 1; sv[2]=-1; sv[3]= 1; break;
        case 2:  qv[0]=2; qv[1]=3; qv[2]=0; qv[3]=1; sv[0]=-1; sv[1]= 1; sv[2]= 1; sv[3]=-1; break;
        default: qv[0]=3; qv[1]=2; qv[2]=1; qv[3]=0; sv[0]=-1; sv[1]=-1; sv[2]= 1; sv[3]= 1; break;
    }

    const float4* src = (const float4*)(Ag + (size_t)n * NNODE);
    #pragma unroll
    for (int mb = 0; mb < 4; ++mb) {
        int m4 = threadIdx.x + mb * 256;
        float4 v = src[m4];
        v.x = to_tf32(v.x); v.y = to_tf32(v.y); v.z = to_tf32(v.z); v.w = to_tf32(v.w);
        #pragma unroll
        for (int p = 0; p < 4; ++p) {
            float s = sv[p];
            float4 w; w.x = v.x * s; w.y = v.y * s; w.z = v.z * s; w.w = v.w * s;
            size_t off = ((size_t)(p * NNODE + n) * KT) + (size_t)qv[p] * NNODE + (size_t)m4 * 4;
            *(float4*)(g_At + off) = w;
        }
    }
}

// ---------------------------------------------------------------------------
// Prepass 2: x[b, q*32+f, m, t] -> g_Xt[q*4096+m][(b*32+f)*12+t], tf32.
// ---------------------------------------------------------------------------
__global__ void pack_x_kernel(const float* __restrict__ x) {
    int j   = blockIdx.x * blockDim.x + threadIdx.x; // 0..6143
    int row = blockIdx.y;                            // 0..16383
    int q = row >> 12;
    int m = row & 4095;
    int b   = j / 384;
    int rem = j - b * 384;
    int f   = rem / TT;
    int t   = rem - f * TT;
    float v = x[(((size_t)(b * 128 + q * 32 + f)) * NNODE + m) * TT + t];
    g_Xt[(size_t)row * JJ + j] = to_tf32(v);
}

// ---------------------------------------------------------------------------
// Main GEMM: Out_p[n, j] = At_p[n, :] @ Xt[:, j]
// CTA 128x256, 8 warps of 64x64 (wm 0..1, wn 0..3), cp.async 4-stage pipeline.
// ---------------------------------------------------------------------------
__global__ void __launch_bounds__(256, 1)
quat_gemm_kernel(float* __restrict__ out)
{
    extern __shared__ float smem[];
    const int tid  = threadIdx.x;
    const int lane = tid & 31;
    const int wid  = tid >> 5;
    const int wm   = wid & 1;   // 0..1 (64-row half)
    const int wn   = wid >> 1;  // 0..3 (64-col quarter)

    // Block swizzle: (nt,p) outer (A read once from DRAM), jt inner.
    const int bid = blockIdx.x;
    const int g   = bid / 24;
    const int jt  = bid - g * 24;
    const int nt  = g >> 2;
    const int p   = g & 3;
    const int n0  = nt * BM;
    const int j0  = jt * BN;

    const float* Abase = g_At + (size_t)(p * NNODE + n0) * KT;   // [128 rows][KT]
    const uint32_t sbase = smem_u32(smem);

    // ---- pipeline copy: per stage 2 A-chunks + 4 B-chunks of 16B per thread ----
    auto issue_stage = [&](int it) {
        const int s  = it & (STAGES - 1);
        const int k0 = it * BK;
        const uint32_t sa = sbase + s * STAGE_B;
        const uint32_t sb = sa + A_STAGE_B;
        #pragma unroll
        for (int i = 0; i < 2; ++i) {            // A: 512 chunks (128 rows x 64B)
            int c = tid + i * 256;
            int row = c >> 2, cc = c & 3;
            cp_async16(sa + row * (A_ROW * 4) + cc * 16,
                       Abase + (size_t)row * KT + k0 + cc * 4);
        }
        #pragma unroll
        for (int i = 0; i < 4; ++i) {            // B: 1024 chunks (16 rows x 1KB)
            int c = tid + i * 256;
            int row = c >> 6, jc = c & 63;
            cp_async16(sb + row * (B_ROW * 4) + jc * 16,
                       g_Xt + (size_t)(k0 + row) * JJ + j0 + jc * 4);
        }
    };

    float acc[4][8][4];
    #pragma unroll
    for (int mi = 0; mi < 4; ++mi)
        #pragma unroll
        for (int ni = 0; ni < 8; ++ni)
            #pragma unroll
            for (int e = 0; e < 4; ++e) acc[mi][ni][e] = 0.f;

    // prologue: fill 3 stages
    #pragma unroll
    for (int it = 0; it < STAGES - 1; ++it) {
        issue_stage(it);
        asm volatile("cp.async.commit_group;" ::: "memory");
    }

    for (int it = 0; it < NIT; ++it) {
        asm volatile("cp.async.wait_group 2;" ::: "memory");
        __syncthreads();

        if (it + STAGES - 1 < NIT) issue_stage(it + STAGES - 1);
        asm volatile("cp.async.commit_group;" ::: "memory");   // empty at tail keeps accounting

        const float* fA = smem + (size_t)(it & (STAGES - 1)) * (STAGE_B / 4);
        const float* fB = fA + A_STAGE_B / 4;

        #pragma unroll
        for (int kk = 0; kk < BK; kk += 8) {
            uint32_t a[4][4], b[8][2];
            #pragma unroll
            for (int mi = 0; mi < 4; ++mi) {
                const float* ap = fA + (wm * 64 + mi * 16 + (lane >> 2)) * A_ROW + kk + (lane & 3);
                a[mi][0] = __float_as_uint(ap[0]);
                a[mi][1] = __float_as_uint(ap[8 * A_ROW]);
                a[mi][2] = __float_as_uint(ap[4]);
                a[mi][3] = __float_as_uint(ap[8 * A_ROW + 4]);
            }
            #pragma unroll
            for (int ni = 0; ni < 8; ++ni) {
                const float* bp = fB + (kk + (lane & 3)) * B_ROW + wn * 64 + ni * 8 + (lane >> 2);
                b[ni][0] = __float_as_uint(bp[0]);
                b[ni][1] = __float_as_uint(bp[4 * B_ROW]);
            }
            #pragma unroll
            for (int mi = 0; mi < 4; ++mi)
                #pragma unroll
                for (int ni = 0; ni < 8; ++ni)
                    mma_tf32(acc[mi][ni], a[mi], b[ni]);
        }
    }

    // ---- epilogue: scatter to out[b, p*32+f, n, t], j = (b*32+f)*12 + t ----
    #pragma unroll
    for (int mi = 0; mi < 4; ++mi) {
        int rbase = n0 + wm * 64 + mi * 16 + (lane >> 2);
        #pragma unroll
        for (int ni = 0; ni < 8; ++ni) {
            int jb = j0 + wn * 64 + ni * 8 + ((lane & 3) << 1);
            #pragma unroll
            for (int e = 0; e < 4; ++e) {
                int n = rbase + ((e >= 2) ? 8 : 0);
                int j = jb + (e & 1);
                int b   = j / 384;
                int rem = j - b * 384;
                int f   = rem / TT;
                int t   = rem - f * TT;
                out[(((size_t)(b * 128 + p * 32 + f)) * NNODE + n) * TT + t] = acc[mi][ni][e];
            }
        }
    }
}

// ---------------------------------------------------------------------------
// Launch
// ---------------------------------------------------------------------------
extern "C" void kernel_launch(void* const* d_in, const int* in_sizes, int n_in,
                              void* d_out, int out_size) {
    const float* x  = (const float*)d_in[0];
    const float* Ar = (const float*)d_in[1];
    const float* Ai = (const float*)d_in[2];
    const float* Aj = (const float*)d_in[3];
    const float* Ak = (const float*)d_in[4];
    float* out = (float*)d_out;

    cudaFuncSetAttribute(quat_gemm_kernel, cudaFuncAttributeMaxDynamicSharedMemorySize, SMEM_DYN);

    // prepasses
    pack_A_kernel<<<dim3(NNODE, 4), 256>>>(Ar, Ai, Aj, Ak);
    pack_x_kernel<<<dim3(JJ / 256, KT), 256>>>(x);

    // GEMM: 32 nt x 4 p (outer) x 24 jt (inner) = 3072 CTAs
    quat_gemm_kernel<<<3072, 256, SMEM_DYN>>>(out);
}

// round 11
// speedup vs baseline: 1.7690x; 1.1815x over previous
#include <cuda_runtime.h>
#include <cstdint>

// ---------------------------------------------------------------------------
// Problem sizes
// ---------------------------------------------------------------------------
#define NNODE 4096
#define TT    12
#define JJ    6144           // B*F*T columns
#define KT    16384          // 4*N contraction
// GEMM tiling
#define BM    128
#define BN    256
#define BK    16
#define NIT   (KT / BK)      // 1024
#define STAGES 4
#define A_STAGE_B (BM * BK * 4)        // 8192  (fragment-major, no padding)
#define B_STAGE_B (BK * BN * 4)        // 16384
#define STAGE_B   (A_STAGE_B + B_STAGE_B)   // 24576
#define SMEM_DYN  (STAGES * STAGE_B)        // 98304

// Fragment-major scratch.
// g_At[((p*256 + n_grp)*2048 + k_blk)*128 + lane*4 + e]:
//   e0 = At[n_grp*16 + (lane>>2)][k_blk*8 + (lane&3)]
//   e1 = row+8, e2 = k+4, e3 = row+8 & k+4        (matches mma A-frag regs)
// g_Xt[(k_blk*384 + j_grp)*128 + lane*4 + e]:
//   e0 = X[k_blk*8 + (lane&3)][j_grp*16 + (lane>>2)]
//   e1 = k+4, e2 = j+8, e3 = k+4 & j+8            (two B-frags per chunk)
__device__ float g_At[(size_t)4 * NNODE * KT];
__device__ float g_Xt[(size_t)KT * JJ];

__device__ __forceinline__ float to_tf32(float x) {
    float r; asm("cvt.rna.tf32.f32 %0, %1;" : "=f"(r) : "f"(x)); return r;
}
__device__ __forceinline__ uint32_t smem_u32(const void* p) {
    uint32_t a;
    asm("{ .reg .u64 t; cvta.to.shared.u64 t, %1; cvt.u32.u64 %0, t; }" : "=r"(a) : "l"(p));
    return a;
}
__device__ __forceinline__ void cp_async16(uint32_t dst, const void* src) {
    asm volatile("cp.async.cg.shared.global [%0], [%1], 16;" :: "r"(dst), "l"(src));
}
__device__ __forceinline__ void mma_tf32(float* d, const uint32_t* a, const uint32_t* b) {
    asm volatile(
        "mma.sync.aligned.m16n8k8.row.col.f32.tf32.tf32.f32 "
        "{%0,%1,%2,%3}, {%4,%5,%6,%7}, {%8,%9}, {%0,%1,%2,%3};\n"
        : "+f"(d[0]), "+f"(d[1]), "+f"(d[2]), "+f"(d[3])
        : "r"(a[0]), "r"(a[1]), "r"(a[2]), "r"(a[3]), "r"(b[0]), "r"(b[1]));
}

// ---------------------------------------------------------------------------
// Prepass 1: signed tf32 A-tilde in fragment-major layout.
// Block: (g, n_grp, m_blk of 512). smem stage 16 rows x 512 cols (pad 516).
// ---------------------------------------------------------------------------
__global__ void __launch_bounds__(256, 2) pack_A_kernel(
    const float* __restrict__ Ar, const float* __restrict__ Ai,
    const float* __restrict__ Aj, const float* __restrict__ Ak)
{
    __shared__ float s[16][516];
    const int n_grp = blockIdx.x;        // 0..255
    const int m_blk = blockIdx.y;        // 0..7
    const int g     = blockIdx.z;        // 0..3
    const int tid   = threadIdx.x;
    const float* Ag = (g == 0) ? Ar : (g == 1) ? Ai : (g == 2) ? Aj : Ak;

    int qv[4]; float sv[4];
    switch (g) {
        case 0:  qv[0]=0; qv[1]=1; qv[2]=2; qv[3]=3; sv[0]= 1; sv[1]= 1; sv[2]= 1; sv[3]= 1; break;
        case 1:  qv[0]=1; qv[1]=0; qv[2]=3; qv[3]=2; sv[0]=-1; sv[1]= 1; sv[2]=-1; sv[3]= 1; break;
        case 2:  qv[0]=2; qv[1]=3; qv[2]=0; qv[3]=1; sv[0]=-1; sv[1]= 1; sv[2]= 1; sv[3]=-1; break;
        default: qv[0]=3; qv[1]=2; qv[2]=1; qv[3]=0; sv[0]=-1; sv[1]=-1; sv[2]= 1; sv[3]= 1; break;
    }

    const int m0 = m_blk * 512;
    // load 16 rows x 512 cols, tf32-rounded
    #pragma unroll
    for (int i = 0; i < 8; ++i) {
        int idx = tid + i * 256;                 // 2048 float4
        int row = idx >> 7, c4 = idx & 127;
        float4 v = *(const float4*)(Ag + (size_t)(n_grp * 16 + row) * NNODE + m0 + c4 * 4);
        s[row][c4 * 4 + 0] = to_tf32(v.x);
        s[row][c4 * 4 + 1] = to_tf32(v.y);
        s[row][c4 * 4 + 2] = to_tf32(v.z);
        s[row][c4 * 4 + 3] = to_tf32(v.w);
    }
    __syncthreads();

    // write 4p x 64 k_blk x 32 lanes fragment chunks
    #pragma unroll
    for (int w = 0; w < 32; ++w) {
        int idx    = tid + w * 256;              // 8192 chunks
        int p      = idx >> 11;
        int kb     = (idx >> 5) & 63;
        int lane_c = idx & 31;
        int r = lane_c >> 2, c = kb * 8 + (lane_c & 3);
        float sg = sv[p];
        float4 o;
        o.x = s[r][c]         * sg;
        o.y = s[r + 8][c]     * sg;
        o.z = s[r][c + 4]     * sg;
        o.w = s[r + 8][c + 4] * sg;
        size_t kblk = (size_t)qv[p] * 512 + m_blk * 64 + kb;
        *(float4*)(g_At + (((size_t)(p * 256 + n_grp)) * 2048 + kblk) * 128 + lane_c * 4) = o;
    }
}

// ---------------------------------------------------------------------------
// Prepass 2: X transpose into fragment-major layout.
// Block: (q, m_blk of 32, b). smem 32 m x 384 j (pad 392).
// ---------------------------------------------------------------------------
__global__ void __launch_bounds__(256, 2) pack_X_kernel(const float* __restrict__ x)
{
    __shared__ float s[32][392];
    const int m_blk = blockIdx.x;        // 0..127
    const int b     = blockIdx.y;        // 0..15
    const int q     = blockIdx.z;        // 0..3
    const int tid   = threadIdx.x;
    const int m0    = m_blk * 32;

    // load x[b, q*32+f, m0..m0+31, 0..11] for all f: 32 runs of 384 floats
    #pragma unroll
    for (int i = 0; i < 48; ++i) {
        int idx  = tid + i * 256;                // 12288 floats
        int f    = idx / 384;
        int iin  = idx - f * 384;                // m_local*12 + t
        int ml   = iin / TT;
        int t    = iin - ml * TT;
        float v  = x[((size_t)(b * 128 + q * 32 + f) * NNODE + m0) * TT + iin];
        s[ml][f * TT + t] = v;
    }
    __syncthreads();

    const size_t kblk0 = (size_t)q * 512 + m_blk * 4;
    const int    jg0   = b * 24;
    #pragma unroll
    for (int w = 0; w < 12; ++w) {
        int idx    = tid + w * 256;              // 3072 chunks: [kb 4][jg 24][lane 32]
        int kb     = idx / 768;
        int rem    = idx - kb * 768;
        int jg     = rem >> 5;
        int lane_c = rem & 31;
        int kr = kb * 8 + (lane_c & 3);
        int jc = jg * 16 + (lane_c >> 2);
        float4 o;
        o.x = to_tf32(s[kr][jc]);
        o.y = to_tf32(s[kr + 4][jc]);
        o.z = to_tf32(s[kr][jc + 8]);
        o.w = to_tf32(s[kr + 4][jc + 8]);
        *(float4*)(g_Xt + ((kblk0 + kb) * 384 + jg0 + jg) * 128 + lane_c * 4) = o;
    }
}

// ---------------------------------------------------------------------------
// Main GEMM: Out_p[n, j] = At_p[n, :] @ Xt[:, j]
// CTA 128x256, 8 warps of 64x64, 4-stage cp.async, LDS.128 fragment loads.
// ---------------------------------------------------------------------------
__global__ void __launch_bounds__(256, 1)
quat_gemm_kernel(float* __restrict__ out)
{
    extern __shared__ char smem[];
    const int tid  = threadIdx.x;
    const int lane = tid & 31;
    const int wid  = tid >> 5;
    const int wm   = wid & 1;   // 0..1 (64-row half)
    const int wn   = wid >> 1;  // 0..3 (64-col quarter)

    // 2-level swizzle: jt blocked by 8 inside the (nt,p) sweep.
    const int bid = blockIdx.x;
    const int jb  = bid >> 10;              // 0..2
    const int r   = bid & 1023;
    const int g   = r >> 3;                 // 0..127
    const int jt  = jb * 8 + (r & 7);       // 0..23
    const int nt  = g >> 2;
    const int p   = g & 3;
    const int n0  = nt * BM;
    const int j0  = jt * BN;

    const float* Afrag = g_At + ((size_t)(p * 256 + (n0 >> 4))) * 2048 * 128;
    const uint32_t sbase = smem_u32(smem);

    auto issue_stage = [&](int it) {
        const int s   = it & (STAGES - 1);
        const int kb0 = it * 2;                        // k_blk base
        const uint32_t sa = sbase + s * STAGE_B;
        const uint32_t sb = sa + A_STAGE_B;
        #pragma unroll
        for (int i = 0; i < 2; ++i) {                  // A: 512 chunks
            int c = tid + i * 256;
            int ngi = c >> 6, kh = (c >> 5) & 1, lc = c & 31;
            cp_async16(sa + (((ngi * 2 + kh) * 32 + lc) << 4),
                       Afrag + ((size_t)ngi * 2048 + kb0 + kh) * 128 + lc * 4);
        }
        #pragma unroll
        for (int i = 0; i < 4; ++i) {                  // B: 1024 chunks
            int c = tid + i * 256;
            int kh = c >> 9, jgi = (c >> 5) & 15, lc = c & 31;
            cp_async16(sb + (((kh * 16 + jgi) * 32 + lc) << 4),
                       g_Xt + ((size_t)(kb0 + kh) * 384 + (j0 >> 4) + jgi) * 128 + lc * 4);
        }
    };

    float acc[4][8][4];
    #pragma unroll
    for (int mi = 0; mi < 4; ++mi)
        #pragma unroll
        for (int ni = 0; ni < 8; ++ni)
            #pragma unroll
            for (int e = 0; e < 4; ++e) acc[mi][ni][e] = 0.f;

    #pragma unroll
    for (int it = 0; it < STAGES - 1; ++it) {
        issue_stage(it);
        asm volatile("cp.async.commit_group;" ::: "memory");
    }

    for (int it = 0; it < NIT; ++it) {
        asm volatile("cp.async.wait_group 2;" ::: "memory");
        __syncthreads();

        if (it + STAGES - 1 < NIT) issue_stage(it + STAGES - 1);
        asm volatile("cp.async.commit_group;" ::: "memory");

        const char* st = smem + (size_t)(it & (STAGES - 1)) * STAGE_B;
        const uint4* fA = (const uint4*)st;
        const uint4* fB = (const uint4*)(st + A_STAGE_B);

        // load ALL fragments for both k-halves (16 x LDS.128), then 64 MMAs
        uint4 a[2][4], b[2][4];
        #pragma unroll
        for (int kh = 0; kh < 2; ++kh) {
            #pragma unroll
            for (int mi = 0; mi < 4; ++mi)
                a[kh][mi] = fA[((wm * 4 + mi) * 2 + kh) * 32 + lane];
            #pragma unroll
            for (int pi = 0; pi < 4; ++pi)
                b[kh][pi] = fB[(kh * 16 + wn * 4 + pi) * 32 + lane];
        }
        #pragma unroll
        for (int kh = 0; kh < 2; ++kh) {
            #pragma unroll
            for (int mi = 0; mi < 4; ++mi) {
                #pragma unroll
                for (int pi = 0; pi < 4; ++pi) {
                    const uint32_t* av = (const uint32_t*)&a[kh][mi];
                    const uint32_t* bv = (const uint32_t*)&b[kh][pi];
                    mma_tf32(acc[mi][2 * pi],     av, bv);      // b regs {x,y}
                    mma_tf32(acc[mi][2 * pi + 1], av, bv + 2);  // b regs {z,w}
                }
            }
        }
    }

    // ---- epilogue: scatter to out[b, p*32+f, n, t], j = (b*32+f)*12 + t ----
    #pragma unroll
    for (int mi = 0; mi < 4; ++mi) {
        int rbase = n0 + wm * 64 + mi * 16 + (lane >> 2);
        #pragma unroll
        for (int ni = 0; ni < 8; ++ni) {
            int jb2 = j0 + wn * 64 + ni * 8 + ((lane & 3) << 1);
            #pragma unroll
            for (int e = 0; e < 4; ++e) {
                int n = rbase + ((e >= 2) ? 8 : 0);
                int j = jb2 + (e & 1);
                int bb  = j / 384;
                int rem = j - bb * 384;
                int f   = rem / TT;
                int t   = rem - f * TT;
                out[(((size_t)(bb * 128 + p * 32 + f)) * NNODE + n) * TT + t] = acc[mi][ni][e];
            }
        }
    }
}

// ---------------------------------------------------------------------------
// Launch
// ---------------------------------------------------------------------------
extern "C" void kernel_launch(void* const* d_in, const int* in_sizes, int n_in,
                              void* d_out, int out_size) {
    const float* x  = (const float*)d_in[0];
    const float* Ar = (const float*)d_in[1];
    const float* Ai = (const float*)d_in[2];
    const float* Aj = (const float*)d_in[3];
    const float* Ak = (const float*)d_in[4];
    float* out = (float*)d_out;

    cudaFuncSetAttribute(quat_gemm_kernel, cudaFuncAttributeMaxDynamicSharedMemorySize, SMEM_DYN);

    pack_A_kernel<<<dim3(256, 8, 4), 256>>>(Ar, Ai, Aj, Ak);
    pack_X_kernel<<<dim3(128, 16, 4), 256>>>(x);

    // 3 jt-blocks x 128 (nt,p) x 8 jt = 3072 CTAs
    quat_gemm_kernel<<<3072, 256, SMEM_DYN>>>(out);
}

// round 14
// speedup vs baseline: 2.3528x; 1.3300x over previous
#include <cuda_runtime.h>
#include <cstdint>

// ---------------------------------------------------------------------------
// Problem sizes
// ---------------------------------------------------------------------------
#define NNODE 4096
#define TT    12
#define JJ    6144            // B*F*T columns per quarter
#define JP    12288           // stacked RHS columns (2 halves)
#define KK    4096            // contraction per GEMM
// GEMM tiling
#define BM    128
#define BN    256
#define BK    16
#define NIT   (KK / BK)       // 256
#define STAGES 4
#define A_STAGE_B (BM * BK * 4)        // 8192
#define B_STAGE_B (BK * BN * 4)        // 16384
#define STAGE_B   (A_STAGE_B + B_STAGE_B)
#define SMEM_DYN  (STAGES * STAGE_B)   // 98304

// Fragment-major scratch.
// g_Am[((mat*256 + n_grp)*512 + k_blk)*128 + lane*4 + e]:
//   e = {A[r][k], A[r+8][k], A[r][k+4], A[r+8][k+4]},
//   r = n_grp*16 + (lane>>2), k = k_blk*8 + (lane&3)
// g_Xm[((mat*512 + k_blk)*768 + j_grp)*128 + lane*4 + e]:
//   e = {X[k][j], X[k+4][j], X[k][j+8], X[k+4][j+8]},
//   k = k_blk*8 + (lane&3), j = j_grp*16 + (lane>>2)
// g_P[mat][n][j'] row-major products.
__device__ float g_Am[(size_t)6 * NNODE * KK];
__device__ float g_Xm[(size_t)6 * KK * JP];
__device__ float g_P [(size_t)6 * NNODE * JP];

__device__ __forceinline__ float to_tf32(float x) {
    float r; asm("cvt.rna.tf32.f32 %0, %1;" : "=f"(r) : "f"(x)); return r;
}
__device__ __forceinline__ float4 t4(float4 v) {
    float4 o; o.x = to_tf32(v.x); o.y = to_tf32(v.y); o.z = to_tf32(v.z); o.w = to_tf32(v.w);
    return o;
}
__device__ __forceinline__ uint32_t smem_u32(const void* p) {
    uint32_t a;
    asm("{ .reg .u64 t; cvta.to.shared.u64 t, %1; cvt.u32.u64 %0, t; }" : "=r"(a) : "l"(p));
    return a;
}
__device__ __forceinline__ void cp_async16(uint32_t dst, const void* src) {
    asm volatile("cp.async.cg.shared.global [%0], [%1], 16;" :: "r"(dst), "l"(src));
}
__device__ __forceinline__ void mma_tf32(float* d, const uint32_t* a, const uint32_t* b) {
    asm volatile(
        "mma.sync.aligned.m16n8k8.row.col.f32.tf32.tf32.f32 "
        "{%0,%1,%2,%3}, {%4,%5,%6,%7}, {%8,%9}, {%0,%1,%2,%3};\n"
        : "+f"(d[0]), "+f"(d[1]), "+f"(d[2]), "+f"(d[3])
        : "r"(a[0]), "r"(a[1]), "r"(a[2]), "r"(a[3]), "r"(b[0]), "r"(b[1]));
}

// ---------------------------------------------------------------------------
// Prepass 1: A-side matrices in fragment-major layout.
//   pair 0: M0 = Ar, M1 = Ai, M2 = Ar+Ai   (tf32-rounded after add)
//   pair 1: M3 = Aj, M4 = Ak, M5 = Aj+Ak
// Block: (n_grp, m_blk of 256 cols, pair). smem: 2 raw tiles 16x260.
// ---------------------------------------------------------------------------
__global__ void __launch_bounds__(256, 2) pack_A_kernel(
    const float* __restrict__ Ar, const float* __restrict__ Ai,
    const float* __restrict__ Aj, const float* __restrict__ Ak)
{
    __shared__ float s[2][16][260];
    const int n_grp = blockIdx.x;        // 0..255
    const int m_blk = blockIdx.y;        // 0..15
    const int pair  = blockIdx.z;        // 0..1
    const int tid   = threadIdx.x;
    const int m0    = m_blk * 256;

    const float* t0 = pair ? Aj : Ar;
    const float* t1 = pair ? Ak : Ai;

    #pragma unroll
    for (int i = 0; i < 8; ++i) {
        int idx  = tid + i * 256;                // 2048 float4
        int tile = idx >> 10;
        int rem  = idx & 1023;
        int row  = rem >> 6, c4 = rem & 63;
        const float* src = (tile ? t1 : t0) + (size_t)(n_grp * 16 + row) * NNODE + m0 + c4 * 4;
        float4 v = *(const float4*)src;
        s[tile][row][c4 * 4 + 0] = v.x;
        s[tile][row][c4 * 4 + 1] = v.y;
        s[tile][row][c4 * 4 + 2] = v.z;
        s[tile][row][c4 * 4 + 3] = v.w;
    }
    __syncthreads();

    #pragma unroll
    for (int i = 0; i < 12; ++i) {
        int idx    = tid + i * 256;              // 3072 chunks
        int matL   = idx >> 10;                  // 0..2
        int rem    = idx & 1023;
        int kb     = rem >> 5;                   // 0..31
        int lane_c = rem & 31;
        int r  = lane_c >> 2;
        int cc = kb * 8 + (lane_c & 3);
        float4 a, b;
        a.x = s[0][r][cc];     a.y = s[0][r + 8][cc];
        a.z = s[0][r][cc + 4]; a.w = s[0][r + 8][cc + 4];
        b.x = s[1][r][cc];     b.y = s[1][r + 8][cc];
        b.z = s[1][r][cc + 4]; b.w = s[1][r + 8][cc + 4];
        float4 o;
        if (matL == 0)      o = t4(a);
        else if (matL == 1) o = t4(b);
        else { float4 c4v; c4v.x = a.x + b.x; c4v.y = a.y + b.y; c4v.z = a.z + b.z; c4v.w = a.w + b.w; o = t4(c4v); }
        int mat = pair * 3 + matL;
        size_t kg = (size_t)(m_blk * 32 + kb);
        *(float4*)(g_Am + (((size_t)(mat * 256 + n_grp)) * 512 + kg) * 128 + lane_c * 4) = o;
    }
}

// ---------------------------------------------------------------------------
// Prepass 2: stacked RHS matrices in fragment-major layout.
//   mat0:[xr|xj] mat1:[xi|xk] mat2:[xr+xi|xj+xk] mat3:[xj|xr] mat4:[xk|xi]
//   mat5:[xj-xk|xr-xi]   (x_q[m][j], j = (b*32+f)*12+t)
// Block: (k_blk of 8 m-rows, b). Dyn smem s[4][8][392].
// ---------------------------------------------------------------------------
__global__ void __launch_bounds__(256, 1) pack_X_kernel(const float* __restrict__ x)
{
    extern __shared__ float s[];                 // [4][8][392]
    const int kb  = blockIdx.x;                  // 0..511
    const int b   = blockIdx.y;                  // 0..15
    const int tid = threadIdx.x;
    const int m0  = kb * 8;
    #define SIDX(q, ml, jl) (((q) * 8 + (ml)) * 392 + (jl))

    // load x[b, c, m0..m0+7, 0..11] for c = 0..127 (two threads per c)
    {
        int c = tid >> 1, half = tid & 1;
        int q = c >> 5, f = c & 31;
        const float4* src = (const float4*)(x + ((size_t)(b * 128 + c) * NNODE + m0) * TT + half * 48);
        #pragma unroll
        for (int w = 0; w < 12; ++w) {
            float4 v = src[w];
            int i0 = half * 48 + w * 4;
            float e[4] = {v.x, v.y, v.z, v.w};
            #pragma unroll
            for (int u = 0; u < 4; ++u) {
                int i  = i0 + u;
                int ml = i / TT;
                int t  = i - ml * TT;
                s[SIDX(q, ml, f * TT + t)] = e[u];
            }
        }
    }
    __syncthreads();

    #pragma unroll
    for (int i = 0; i < 3; ++i) {
        int pos    = tid + i * 256;              // 0..767
        int jg     = pos >> 5;                   // 0..23
        int lane_c = pos & 31;
        int ml  = lane_c & 3;
        int jl1 = jg * 16 + (lane_c >> 2);
        int jl2 = jl1 + 8;

        float4 V[4];
        #pragma unroll
        for (int q = 0; q < 4; ++q) {
            V[q].x = s[SIDX(q, ml,     jl1)];
            V[q].y = s[SIDX(q, ml + 4, jl1)];
            V[q].z = s[SIDX(q, ml,     jl2)];
            V[q].w = s[SIDX(q, ml + 4, jl2)];
        }
        float4 wr = t4(V[0]), wi = t4(V[1]), wj = t4(V[2]), wk = t4(V[3]);
        float4 tmp;
        tmp.x = V[0].x + V[1].x; tmp.y = V[0].y + V[1].y; tmp.z = V[0].z + V[1].z; tmp.w = V[0].w + V[1].w;
        float4 wri = t4(tmp);
        tmp.x = V[2].x + V[3].x; tmp.y = V[2].y + V[3].y; tmp.z = V[2].z + V[3].z; tmp.w = V[2].w + V[3].w;
        float4 wjk = t4(tmp);
        tmp.x = V[2].x - V[3].x; tmp.y = V[2].y - V[3].y; tmp.z = V[2].z - V[3].z; tmp.w = V[2].w - V[3].w;
        float4 wjmk = t4(tmp);
        tmp.x = V[0].x - V[1].x; tmp.y = V[0].y - V[1].y; tmp.z = V[0].z - V[1].z; tmp.w = V[0].w - V[1].w;
        float4 wrmi = t4(tmp);

        #define XADDR(mat, half) (g_Xm + (((size_t)(mat) * 512 + kb) * 768 + (half) * 384 + b * 24 + jg) * 128 + lane_c * 4)
        *(float4*)XADDR(0, 0) = wr;   *(float4*)XADDR(0, 1) = wj;
        *(float4*)XADDR(1, 0) = wi;   *(float4*)XADDR(1, 1) = wk;
        *(float4*)XADDR(2, 0) = wri;  *(float4*)XADDR(2, 1) = wjk;
        *(float4*)XADDR(3, 0) = wj;   *(float4*)XADDR(3, 1) = wr;
        *(float4*)XADDR(4, 0) = wk;   *(float4*)XADDR(4, 1) = wi;
        *(float4*)XADDR(5, 0) = wjmk; *(float4*)XADDR(5, 1) = wrmi;
        #undef XADDR
    }
    #undef SIDX
}

// ---------------------------------------------------------------------------
// GEMM: P[mat] = M[mat] @ RHS[mat], CTA 128x256, 8 warps 64x64,
// 4-stage cp.async, LDS.128 fragment loads, contiguous P epilogue.
// ---------------------------------------------------------------------------
__global__ void __launch_bounds__(256, 1)
quat_gemm_kernel()
{
    extern __shared__ char smem[];
    const int tid  = threadIdx.x;
    const int lane = tid & 31;
    const int wid  = tid >> 5;
    const int wm   = wid & 1;
    const int wn   = wid >> 1;

    // swizzle: 6 jt-blocks of 8; inside, (mat,nt) sweep nt-minor.
    const int bid = blockIdx.x;
    const int jb  = bid / 1536;             // 0..5
    const int r   = bid - jb * 1536;
    const int g   = r >> 3;                 // 0..191
    const int jt  = jb * 8 + (r & 7);       // 0..47
    const int mat = g >> 5;                 // 0..5
    const int nt  = g & 31;                 // 0..31
    const int n0  = nt * BM;
    const int j0  = jt * BN;
    const int jg0 = j0 >> 4;

    const float* Afrag = g_Am + ((size_t)(mat * 256 + (n0 >> 4))) * 512 * 128;
    const float* Bfrag = g_Xm + ((size_t)mat * 512) * 768 * 128;
    const uint32_t sbase = smem_u32(smem);

    auto issue_stage = [&](int it) {
        const int s   = it & (STAGES - 1);
        const int kb0 = it * 2;
        const uint32_t sa = sbase + s * STAGE_B;
        const uint32_t sb = sa + A_STAGE_B;
        #pragma unroll
        for (int i = 0; i < 2; ++i) {                  // A: 512 chunks
            int c = tid + i * 256;
            int ngi = c >> 6, kh = (c >> 5) & 1, lc = c & 31;
            cp_async16(sa + (((ngi * 2 + kh) * 32 + lc) << 4),
                       Afrag + ((size_t)ngi * 512 + kb0 + kh) * 128 + lc * 4);
        }
        #pragma unroll
        for (int i = 0; i < 4; ++i) {                  // B: 1024 chunks
            int c = tid + i * 256;
            int kh = c >> 9, jgi = (c >> 5) & 15, lc = c & 31;
            cp_async16(sb + (((kh * 16 + jgi) * 32 + lc) << 4),
                       Bfrag + ((size_t)(kb0 + kh) * 768 + jg0 + jgi) * 128 + lc * 4);
        }
    };

    float acc[4][8][4];
    #pragma unroll
    for (int mi = 0; mi < 4; ++mi)
        #pragma unroll
        for (int ni = 0; ni < 8; ++ni)
            #pragma unroll
            for (int e = 0; e < 4; ++e) acc[mi][ni][e] = 0.f;

    #pragma unroll
    for (int it = 0; it < STAGES - 1; ++it) {
        issue_stage(it);
        asm volatile("cp.async.commit_group;" ::: "memory");
    }

    for (int it = 0; it < NIT; ++it) {
        asm volatile("cp.async.wait_group 2;" ::: "memory");
        __syncthreads();

        if (it + STAGES - 1 < NIT) issue_stage(it + STAGES - 1);
        asm volatile("cp.async.commit_group;" ::: "memory");

        const char* st = smem + (size_t)(it & (STAGES - 1)) * STAGE_B;
        const uint4* fA = (const uint4*)st;
        const uint4* fB = (const uint4*)(st + A_STAGE_B);

        uint4 a[2][4], b[2][4];
        #pragma unroll
        for (int kh = 0; kh < 2; ++kh) {
            #pragma unroll
            for (int mi = 0; mi < 4; ++mi)
                a[kh][mi] = fA[((wm * 4 + mi) * 2 + kh) * 32 + lane];
            #pragma unroll
            for (int pi = 0; pi < 4; ++pi)
                b[kh][pi] = fB[(kh * 16 + wn * 4 + pi) * 32 + lane];
        }
        #pragma unroll
        for (int kh = 0; kh < 2; ++kh) {
            #pragma unroll
            for (int mi = 0; mi < 4; ++mi) {
                #pragma unroll
                for (int pi = 0; pi < 4; ++pi) {
                    const uint32_t* av = (const uint32_t*)&a[kh][mi];
                    const uint32_t* bv = (const uint32_t*)&b[kh][pi];
                    mma_tf32(acc[mi][2 * pi],     av, bv);
                    mma_tf32(acc[mi][2 * pi + 1], av, bv + 2);
                }
            }
        }
    }

    // contiguous epilogue into g_P[mat][row][col]
    float* Pbase = g_P + (size_t)mat * NNODE * JP;
    #pragma unroll
    for (int mi = 0; mi < 4; ++mi) {
        int r0 = n0 + wm * 64 + mi * 16 + (lane >> 2);
        #pragma unroll
        for (int ni = 0; ni < 8; ++ni) {
            int col = j0 + wn * 64 + ni * 8 + ((lane & 3) << 1);
            float2 v0 = make_float2(acc[mi][ni][0], acc[mi][ni][1]);
            float2 v1 = make_float2(acc[mi][ni][2], acc[mi][ni][3]);
            *(float2*)(Pbase + (size_t)r0 * JP + col)       = v0;
            *(float2*)(Pbase + (size_t)(r0 + 8) * JP + col) = v1;
        }
    }
}

// ---------------------------------------------------------------------------
// Combine: out quarters from the 12 product halves, scatter to out layout.
// ---------------------------------------------------------------------------
__global__ void __launch_bounds__(128, 8) combine_kernel(float* __restrict__ out)
{
    const int n = blockIdx.y;
    const int j = blockIdx.x * 128 + threadIdx.x;      // 0..6143
    const size_t str = (size_t)NNODE * JP;
    const float* Pn = g_P + (size_t)n * JP + j;

    float p0a = Pn[0],       p0b = Pn[JJ];
    float p1a = Pn[str],     p1b = Pn[str + JJ];
    float p2a = Pn[2 * str], p2b = Pn[2 * str + JJ];
    float p3a = Pn[3 * str], p3b = Pn[3 * str + JJ];
    float p4a = Pn[4 * str], p4b = Pn[4 * str + JJ];
    float p5a = Pn[5 * str], p5b = Pn[5 * str + JJ];

    float out_r = p0a - p1a - p3a - p4a;
    float out_i = p2a - p0a - p1a + p3a - p4a - p5a;
    float out_j = p0b - p1b + p3b + p4b;
    float out_k = p2b - p0b - p1b - p3b + p4b + p5b;

    int b   = j / 384;
    int rem = j - b * 384;
    int f   = rem / TT;
    int t   = rem - f * TT;
    size_t obase = ((size_t)(b * 128 + f) * NNODE + n) * TT + t;
    const size_t pstr = (size_t)32 * NNODE * TT;
    out[obase]            = out_r;
    out[obase + pstr]     = out_i;
    out[obase + 2 * pstr] = out_j;
    out[obase + 3 * pstr] = out_k;
}

// ---------------------------------------------------------------------------
// Launch
// ---------------------------------------------------------------------------
extern "C" void kernel_launch(void* const* d_in, const int* in_sizes, int n_in,
                              void* d_out, int out_size) {
    const float* x  = (const float*)d_in[0];
    const float* Ar = (const float*)d_in[1];
    const float* Ai = (const float*)d_in[2];
    const float* Aj = (const float*)d_in[3];
    const float* Ak = (const float*)d_in[4];
    float* out = (float*)d_out;

    cudaFuncSetAttribute(quat_gemm_kernel, cudaFuncAttributeMaxDynamicSharedMemorySize, SMEM_DYN);
    cudaFuncSetAttribute(pack_X_kernel, cudaFuncAttributeMaxDynamicSharedMemorySize, 4 * 8 * 392 * 4);

    pack_A_kernel<<<dim3(256, 16, 2), 256>>>(Ar, Ai, Aj, Ak);
    pack_X_kernel<<<dim3(512, 16), 256, 4 * 8 * 392 * 4>>>(x);

    // 6 jt-blocks x 192 (mat,nt) x 8 jt = 9216 CTAs
    quat_gemm_kernel<<<9216, 256, SMEM_DYN>>>();

    combine_kernel<<<dim3(48, 4096), 128>>>(out);
}

// round 16
// speedup vs baseline: 2.8187x; 1.1980x over previous
#include <cuda_runtime.h>
#include <cstdint>

// ---------------------------------------------------------------------------
// Problem sizes
// ---------------------------------------------------------------------------
#define NNODE 4096
#define TT    12
#define JJ    6144            // columns per product
#define KK    4096            // contraction per GEMM
// GEMM tiling
#define BM    128
#define BN    256
#define BK    32
#define NIT   (KK / BK)       // 128
#define STAGES 4
#define A_STAGE_B (BM * BK * 4)        // 16384
#define B_STAGE_B (BK * BN * 4)        // 32768
#define STAGE_B   (A_STAGE_B + B_STAGE_B)   // 49152
#define SMEM_DYN  (STAGES * STAGE_B)        // 196608

// 7 A-side combos, 11 X column-groups, 11 products.
// A: 0:Ar 1:Ar+Ai 2:Ar-Ai 3:Ai-Ak 4:Ai+Ak 5:Ar-Aj 6:Ar+Aj
// X cg: 0:xr+xi+xj+xk 1:xi+xk 2:-(xr+xj) 3:xk 4:xr 5:-xj 6:-xi 7:xr 8:-xk 9:xi 10:-xj
// Products P[m] = A[amap[m]] @ X[cg m]; amap = {0,1,2,3,3,4,4,5,5,6,6}
// out_r = (P0-P1) + P10 + P3 ; out_i = (P0+P2) + P5 + P8
// out_j = (P0-P1) - P7 - P6  ; out_k = (P0+P2) - P4 - P9
// (re-verified term-by-term against the Hamilton reference this round)
__device__ float g_Am[(size_t)7 * NNODE * KK];
__device__ float g_Xm[(size_t)11 * KK * JJ];
__device__ float g_P [(size_t)11 * NNODE * JJ];

__device__ __forceinline__ float to_tf32(float x) {
    float r; asm("cvt.rna.tf32.f32 %0, %1;" : "=f"(r) : "f"(x)); return r;
}
__device__ __forceinline__ float4 t4(float4 v) {
    float4 o; o.x = to_tf32(v.x); o.y = to_tf32(v.y); o.z = to_tf32(v.z); o.w = to_tf32(v.w);
    return o;
}
__device__ __forceinline__ float4 f4add(float4 a, float4 b) {
    float4 o; o.x = a.x + b.x; o.y = a.y + b.y; o.z = a.z + b.z; o.w = a.w + b.w; return o;
}
__device__ __forceinline__ float4 f4neg(float4 a) {
    float4 o; o.x = -a.x; o.y = -a.y; o.z = -a.z; o.w = -a.w; return o;
}
__device__ __forceinline__ uint32_t smem_u32(const void* p) {
    uint32_t a;
    asm("{ .reg .u64 t; cvta.to.shared.u64 t, %1; cvt.u32.u64 %0, t; }" : "=r"(a) : "l"(p));
    return a;
}
__device__ __forceinline__ void cp_async16(uint32_t dst, const void* src) {
    asm volatile("cp.async.cg.shared.global [%0], [%1], 16;" :: "r"(dst), "l"(src));
}
__device__ __forceinline__ void mma_tf32(float* d, const uint32_t* a, const uint32_t* b) {
    asm volatile(
        "mma.sync.aligned.m16n8k8.row.col.f32.tf32.tf32.f32 "
        "{%0,%1,%2,%3}, {%4,%5,%6,%7}, {%8,%9}, {%0,%1,%2,%3};\n"
        : "+f"(d[0]), "+f"(d[1]), "+f"(d[2]), "+f"(d[3])
        : "r"(a[0]), "r"(a[1]), "r"(a[2]), "r"(a[3]), "r"(b[0]), "r"(b[1]));
}

// ---------------------------------------------------------------------------
// Prepass 1: 7 A-combos in fragment-major layout.
// z=0: (Ar,Ai) -> mats 0:copy, 1:sum, 2:diff ; z=1: (Ai,Ak) -> 3:diff, 4:sum
// z=2: (Ar,Aj) -> 5:diff, 6:sum
// ---------------------------------------------------------------------------
__global__ void __launch_bounds__(256, 2) pack_A_kernel(
    const float* __restrict__ Ar, const float* __restrict__ Ai,
    const float* __restrict__ Aj, const float* __restrict__ Ak)
{
    __shared__ float s[2][16][260];
    const int n_grp = blockIdx.x;        // 0..255
    const int m_blk = blockIdx.y;        // 0..15 (256 cols each)
    const int z     = blockIdx.z;        // 0..2
    const int tid   = threadIdx.x;
    const int m0    = m_blk * 256;

    const float* t0 = (z == 1) ? Ai : Ar;
    const float* t1 = (z == 0) ? Ai : (z == 1) ? Ak : Aj;
    const int nm    = (z == 0) ? 3 : 2;
    const int mbase = (z == 0) ? 0 : (z == 1) ? 3 : 5;

    #pragma unroll
    for (int i = 0; i < 8; ++i) {
        int idx  = tid + i * 256;                // 2048 float4
        int tile = idx >> 10;
        int rem  = idx & 1023;
        int row  = rem >> 6, c4 = rem & 63;
        const float* src = (tile ? t1 : t0) + (size_t)(n_grp * 16 + row) * NNODE + m0 + c4 * 4;
        float4 v = *(const float4*)src;
        s[tile][row][c4 * 4 + 0] = v.x;
        s[tile][row][c4 * 4 + 1] = v.y;
        s[tile][row][c4 * 4 + 2] = v.z;
        s[tile][row][c4 * 4 + 3] = v.w;
    }
    __syncthreads();

    for (int i = 0; i < 12; ++i) {
        int idx = tid + i * 256;
        if (idx >= nm * 1024) break;
        int matL   = idx >> 10;
        int rem    = idx & 1023;
        int kb     = rem >> 5;                   // 0..31 (k_blk within 256 cols)
        int lane_c = rem & 31;
        int r  = lane_c >> 2;
        int cc = kb * 8 + (lane_c & 3);
        float4 a, b;
        a.x = s[0][r][cc];     a.y = s[0][r + 8][cc];
        a.z = s[0][r][cc + 4]; a.w = s[0][r + 8][cc + 4];
        b.x = s[1][r][cc];     b.y = s[1][r + 8][cc];
        b.z = s[1][r][cc + 4]; b.w = s[1][r + 8][cc + 4];
        float4 o;
        if (z == 0) {
            if (matL == 0)      o = t4(a);
            else if (matL == 1) o = t4(f4add(a, b));
            else                o = t4(f4add(a, f4neg(b)));
        } else {
            if (matL == 0)      o = t4(f4add(a, f4neg(b)));
            else                o = t4(f4add(a, b));
        }
        int mat = mbase + matL;
        size_t kblk = (size_t)(m_blk * 32 + kb);
        *(float4*)(g_Am + (((size_t)(mat * 256 + n_grp)) * 512 + kblk) * 128 + lane_c * 4) = o;
    }
}

// ---------------------------------------------------------------------------
// Prepass 2: 11 X column-groups in fragment-major layout.
// ---------------------------------------------------------------------------
__global__ void __launch_bounds__(256, 1) pack_X_kernel(const float* __restrict__ x)
{
    extern __shared__ float s[];                 // [4][8][392]
    const int kb  = blockIdx.x;                  // 0..511
    const int b   = blockIdx.y;                  // 0..15
    const int tid = threadIdx.x;
    const int m0  = kb * 8;
    #define SIDX(q, ml, jl) (((q) * 8 + (ml)) * 392 + (jl))

    {
        int c = tid >> 1, half = tid & 1;
        int q = c >> 5, f = c & 31;
        const float4* src = (const float4*)(x + ((size_t)(b * 128 + c) * NNODE + m0) * TT + half * 48);
        #pragma unroll
        for (int w = 0; w < 12; ++w) {
            float4 v = src[w];
            int i0 = half * 48 + w * 4;
            float e[4] = {v.x, v.y, v.z, v.w};
            #pragma unroll
            for (int u = 0; u < 4; ++u) {
                int i  = i0 + u;
                int ml = i / TT;
                int t  = i - ml * TT;
                s[SIDX(q, ml, f * TT + t)] = e[u];
            }
        }
    }
    __syncthreads();

    #pragma unroll
    for (int i = 0; i < 3; ++i) {
        int pos    = tid + i * 256;              // 0..767
        int jg     = pos >> 5;                   // 0..23
        int lane_c = pos & 31;
        int ml  = lane_c & 3;
        int jl1 = jg * 16 + (lane_c >> 2);
        int jl2 = jl1 + 8;

        float4 V[4];
        #pragma unroll
        for (int q = 0; q < 4; ++q) {
            V[q].x = s[SIDX(q, ml,     jl1)];
            V[q].y = s[SIDX(q, ml + 4, jl1)];
            V[q].z = s[SIDX(q, ml,     jl2)];
            V[q].w = s[SIDX(q, ml + 4, jl2)];
        }
        float4 wr = t4(V[0]), wi = t4(V[1]), wj = t4(V[2]), wk = t4(V[3]);
        float4 sum4 = t4(f4add(f4add(V[0], V[1]), f4add(V[2], V[3])));
        float4 sik  = t4(f4add(V[1], V[3]));
        float4 nsrj = t4(f4neg(f4add(V[0], V[2])));

        #define XADDR(cg) (g_Xm + (((size_t)(cg) * 512 + kb) * 384 + b * 24 + jg) * 128 + lane_c * 4)
        *(float4*)XADDR(0)  = sum4;
        *(float4*)XADDR(1)  = sik;
        *(float4*)XADDR(2)  = nsrj;
        *(float4*)XADDR(3)  = wk;
        *(float4*)XADDR(4)  = wr;
        *(float4*)XADDR(5)  = f4neg(wj);
        *(float4*)XADDR(6)  = f4neg(wi);
        *(float4*)XADDR(7)  = wr;
        *(float4*)XADDR(8)  = f4neg(wk);
        *(float4*)XADDR(9)  = wi;
        *(float4*)XADDR(10) = f4neg(wj);
        #undef XADDR
    }
    #undef SIDX
}

// ---------------------------------------------------------------------------
// GEMM: P[m] = A[amap[m]] @ X[cg m].  CTA 128x256, 8 warps 64x64,
// BK=32, 4-stage cp.async, fragment double-buffering over 4 k-blocks.
// ---------------------------------------------------------------------------
__global__ void __launch_bounds__(256, 1)
quat_gemm_kernel()
{
    extern __shared__ char smem[];
    const int tid  = threadIdx.x;
    const int lane = tid & 31;
    const int wid  = tid >> 5;
    const int wm   = wid & 1;
    const int wn   = wid >> 1;

    // swizzle: 3 jt-blocks of 8; inside, (mat,nt) sweep nt-minor.
    const int bid  = blockIdx.x;
    const int jb   = bid / 2816;            // 0..2
    const int r    = bid - jb * 2816;
    const int g    = r >> 3;                // 0..351
    const int jt   = jb * 8 + (r & 7);      // 0..23
    const int mat  = g >> 5;                // 0..10
    const int nt   = g & 31;                // 0..31
    const int n0   = nt * BM;
    const int j0   = jt * BN;
    const int jg0  = j0 >> 4;

    const int amap[11] = {0, 1, 2, 3, 3, 4, 4, 5, 5, 6, 6};
    const float* Afrag = g_Am + ((size_t)(amap[mat] * 256 + (n0 >> 4))) * 512 * 128;
    const float* Bfrag = g_Xm + ((size_t)mat * 512) * 384 * 128;
    const uint32_t sbase = smem_u32(smem);

    auto issue_stage = [&](int it) {
        const int s   = it & (STAGES - 1);
        const int kb0 = it * 4;                        // 4 k_blks per stage
        const uint32_t sa = sbase + s * STAGE_B;
        const uint32_t sb = sa + A_STAGE_B;
        #pragma unroll
        for (int i = 0; i < 4; ++i) {                  // A: 1024 chunks
            int c = tid + i * 256;
            int ngi = c >> 7, kh = (c >> 5) & 3, lc = c & 31;
            cp_async16(sa + (((ngi * 4 + kh) * 32 + lc) << 4),
                       Afrag + ((size_t)ngi * 512 + kb0 + kh) * 128 + lc * 4);
        }
        #pragma unroll
        for (int i = 0; i < 8; ++i) {                  // B: 2048 chunks
            int c = tid + i * 256;
            int kh = c >> 9, jgi = (c >> 5) & 15, lc = c & 31;
            cp_async16(sb + (((kh * 16 + jgi) * 32 + lc) << 4),
                       Bfrag + ((size_t)(kb0 + kh) * 384 + jg0 + jgi) * 128 + lc * 4);
        }
    };

    float acc[4][8][4];
    #pragma unroll
    for (int mi = 0; mi < 4; ++mi)
        #pragma unroll
        for (int ni = 0; ni < 8; ++ni)
            #pragma unroll
            for (int e = 0; e < 4; ++e) acc[mi][ni][e] = 0.f;

    #pragma unroll
    for (int it = 0; it < STAGES - 1; ++it) {
        issue_stage(it);
        asm volatile("cp.async.commit_group;" ::: "memory");
    }

    for (int it = 0; it < NIT; ++it) {
        asm volatile("cp.async.wait_group 2;" ::: "memory");
        __syncthreads();

        if (it + STAGES - 1 < NIT) issue_stage(it + STAGES - 1);
        asm volatile("cp.async.commit_group;" ::: "memory");

        const char* st = smem + (size_t)(it & (STAGES - 1)) * STAGE_B;
        const uint4* fA = (const uint4*)st;
        const uint4* fB = (const uint4*)(st + A_STAGE_B);

        uint4 a[2][4], b[2][4];
        // preload k-block 0
        #pragma unroll
        for (int mi = 0; mi < 4; ++mi)
            a[0][mi] = fA[((wm * 4 + mi) * 4 + 0) * 32 + lane];
        #pragma unroll
        for (int pi = 0; pi < 4; ++pi)
            b[0][pi] = fB[(0 * 16 + wn * 4 + pi) * 32 + lane];

        #pragma unroll
        for (int kh = 0; kh < 4; ++kh) {
            const int cur = kh & 1, nxt = cur ^ 1;
            if (kh < 3) {      // prefetch next k-block while computing
                #pragma unroll
                for (int mi = 0; mi < 4; ++mi)
                    a[nxt][mi] = fA[((wm * 4 + mi) * 4 + kh + 1) * 32 + lane];
                #pragma unroll
                for (int pi = 0; pi < 4; ++pi)
                    b[nxt][pi] = fB[((kh + 1) * 16 + wn * 4 + pi) * 32 + lane];
            }
            #pragma unroll
            for (int mi = 0; mi < 4; ++mi) {
                #pragma unroll
                for (int pi = 0; pi < 4; ++pi) {
                    const uint32_t* av = (const uint32_t*)&a[cur][mi];
                    const uint32_t* bv = (const uint32_t*)&b[cur][pi];
                    mma_tf32(acc[mi][2 * pi],     av, bv);
                    mma_tf32(acc[mi][2 * pi + 1], av, bv + 2);
                }
            }
        }
    }

    // contiguous epilogue into g_P[mat][row][col]
    float* Pbase = g_P + (size_t)mat * NNODE * JJ;
    #pragma unroll
    for (int mi = 0; mi < 4; ++mi) {
        int r0 = n0 + wm * 64 + mi * 16 + (lane >> 2);
        #pragma unroll
        for (int ni = 0; ni < 8; ++ni) {
            int col = j0 + wn * 64 + ni * 8 + ((lane & 3) << 1);
            float2 v0 = make_float2(acc[mi][ni][0], acc[mi][ni][1]);
            float2 v1 = make_float2(acc[mi][ni][2], acc[mi][ni][3]);
            *(float2*)(Pbase + (size_t)r0 * JJ + col)       = v0;
            *(float2*)(Pbase + (size_t)(r0 + 8) * JJ + col) = v1;
        }
    }
}

// ---------------------------------------------------------------------------
// Combine: 11 products -> 4 output quarters, scatter to out layout.
// ---------------------------------------------------------------------------
__global__ void __launch_bounds__(128, 8) combine_kernel(float* __restrict__ out)
{
    const int n = blockIdx.y;
    const int j = blockIdx.x * 128 + threadIdx.x;      // 0..6143
    const size_t str = (size_t)NNODE * JJ;
    const float* Pn = g_P + (size_t)n * JJ + j;

    float p0  = Pn[0];
    float p1  = Pn[str];
    float p2  = Pn[2 * str];
    float p3  = Pn[3 * str];
    float p4  = Pn[4 * str];
    float p5  = Pn[5 * str];
    float p6  = Pn[6 * str];
    float p7  = Pn[7 * str];
    float p8  = Pn[8 * str];
    float p9  = Pn[9 * str];
    float p10 = Pn[10 * str];

    float t1a = p0 - p1;    // T1 first component
    float t1b = p0 + p2;    // T1 second component

    float out_r = t1a + p10 + p3;
    float out_i = t1b + p5 + p8;
    float out_j = t1a - p7 - p6;
    float out_k = t1b - p4 - p9;

    int b   = j / 384;
    int rem = j - b * 384;
    int f   = rem / TT;
    int t   = rem - f * TT;
    size_t obase = ((size_t)(b * 128 + f) * NNODE + n) * TT + t;
    const size_t pstr = (size_t)32 * NNODE * TT;
    out[obase]            = out_r;
    out[obase + pstr]     = out_i;
    out[obase + 2 * pstr] = out_j;
    out[obase + 3 * pstr] = out_k;
}

// ---------------------------------------------------------------------------
// Launch
// ---------------------------------------------------------------------------
extern "C" void kernel_launch(void* const* d_in, const int* in_sizes, int n_in,
                              void* d_out, int out_size) {
    const float* x  = (const float*)d_in[0];
    const float* Ar = (const float*)d_in[1];
    const float* Ai = (const float*)d_in[2];
    const float* Aj = (const float*)d_in[3];
    const float* Ak = (const float*)d_in[4];
    float* out = (float*)d_out;

    cudaFuncSetAttribute(quat_gemm_kernel, cudaFuncAttributeMaxDynamicSharedMemorySize, SMEM_DYN);
    cudaFuncSetAttribute(pack_X_kernel, cudaFuncAttributeMaxDynamicSharedMemorySize, 4 * 8 * 392 * 4);

    pack_A_kernel<<<dim3(256, 16, 3), 256>>>(Ar, Ai, Aj, Ak);
    pack_X_kernel<<<dim3(512, 16), 256, 4 * 8 * 392 * 4>>>(x);

    // 3 jt-blocks x 352 (mat,nt) x 8 jt = 8448 CTAs
    quat_gemm_kernel<<<8448, 256, SMEM_DYN>>>();

    combine_kernel<<<dim3(48, 4096), 128>>>(out);
}